// round 1
// baseline (speedup 1.0000x reference)
#include <cuda_runtime.h>
#include <math.h>

#define NB    64
#define NI    2048
#define KA    8
#define NO    32
#define OA    16
#define OUT   512            // NO*OA

// Scratch (static device arrays — allowed; no runtime allocation)
__device__ float g_votes[(size_t)NB * NI * OUT];   // 256 MB
__device__ float g_S[NB * OUT];                    // cumulative sum of activations
__device__ float g_preact[NB * OUT];

// ---------------------------------------------------------------- zero
__global__ void k_zero() {
    int t = blockIdx.x * blockDim.x + threadIdx.x;
    if (t < NB * OUT) { g_S[t] = 0.0f; g_preact[t] = 0.0f; }
}

// ---------------------------------------------------------------- votes
// grid = NI blocks, block = 256 threads. Thread t owns output pair (2t, 2t+1).
// W[i] (8x512) cached in registers, reused across all 64 batch elements.
__global__ void k_votes(const float* __restrict__ x, const float* __restrict__ W) {
    const int i = blockIdx.x;
    const int t = threadIdx.x;

    float2 w[KA];
    const float2* W2 = reinterpret_cast<const float2*>(W);
#pragma unroll
    for (int k = 0; k < KA; k++)
        w[k] = W2[(size_t)(i * KA + k) * (OUT / 2) + t];

    float2* votes2 = reinterpret_cast<float2*>(g_votes);
    for (int b = 0; b < NB; b++) {
        const float4* xp = reinterpret_cast<const float4*>(&x[((size_t)b * NI + i) * KA]);
        float4 xa = __ldg(xp);
        float4 xb = __ldg(xp + 1);
        float xk[KA] = {xa.x, xa.y, xa.z, xa.w, xb.x, xb.y, xb.z, xb.w};
        float2 v = make_float2(0.0f, 0.0f);
#pragma unroll
        for (int k = 0; k < KA; k++) {
            v.x = fmaf(xk[k], w[k].x, v.x);
            v.y = fmaf(xk[k], w[k].y, v.y);
        }
        votes2[((size_t)b * NI + i) * (OUT / 2) + t] = v;
    }
}

// ---------------------------------------------------------------- routing pass
// grid = (8, 64), block = 256 (8 warps). Warp handles 32 consecutive i for one b.
// lane = j (output capsule). logits = votes . S  (S = sum of previous activations),
// leaky softmax over 32 lanes (leak contributes +1 to denominator),
// preact += route * votes accumulated in registers, flushed with atomics.
#define ICH 8
#define CHUNK (NI / ICH)       // 256
#define WPB 8
#define IPW (CHUNK / WPB)      // 32

__global__ void k_route() {
    const int b    = blockIdx.y;
    const int w    = threadIdx.x >> 5;
    const int lane = threadIdx.x & 31;          // lane == j
    const int ibase = blockIdx.x * CHUNK + w * IPW;

    // S[b, j, 0..15] in registers
    float s[OA];
    {
        const float4* Sp = reinterpret_cast<const float4*>(&g_S[b * OUT + lane * OA]);
#pragma unroll
        for (int q = 0; q < 4; q++) {
            float4 sv = Sp[q];
            s[4*q+0] = sv.x; s[4*q+1] = sv.y; s[4*q+2] = sv.z; s[4*q+3] = sv.w;
        }
    }

    float acc[OA];
#pragma unroll
    for (int a = 0; a < OA; a++) acc[a] = 0.0f;

    for (int m = 0; m < IPW; m++) {
        const int i = ibase + m;
        const float4* vp = reinterpret_cast<const float4*>(
            &g_votes[((size_t)b * NI + i) * OUT + lane * OA]);
        float v[OA];
#pragma unroll
        for (int q = 0; q < 4; q++) {
            float4 vv = __ldg(vp + q);
            v[4*q+0] = vv.x; v[4*q+1] = vv.y; v[4*q+2] = vv.z; v[4*q+3] = vv.w;
        }
        // logit_j = sum_a v[a]*s[a]
        float lg = 0.0f;
#pragma unroll
        for (int a = 0; a < OA; a++) lg = fmaf(v[a], s[a], lg);

        float e = __expf(lg);
        float tot = e;
#pragma unroll
        for (int d = 16; d > 0; d >>= 1)
            tot += __shfl_xor_sync(0xFFFFFFFFu, tot, d);
        float r = e / (1.0f + tot);            // leaky softmax (leak logit = 0)

#pragma unroll
        for (int a = 0; a < OA; a++) acc[a] = fmaf(r, v[a], acc[a]);
    }

    float* dst = &g_preact[b * OUT + lane * OA];
#pragma unroll
    for (int a = 0; a < OA; a++) atomicAdd(dst + a, acc[a]);
}

// ---------------------------------------------------------------- squash
// grid = 64 (b), block = 512. thread t -> (j = t/16, a = t%16).
__global__ void k_squash(const float* __restrict__ bias, float* __restrict__ out) {
    const int b = blockIdx.x;
    const int t = threadIdx.x;

    float p = g_preact[b * OUT + t] + bias[t];
    float sq = p * p;
#pragma unroll
    for (int d = 1; d < OA; d <<= 1)
        sq += __shfl_xor_sync(0xFFFFFFFFu, sq, d);   // sum over 16-lane group
    float nrm = sqrtf(sq);
    float scale = nrm / (1.0f + sq);                 // v/||v|| * ||v||^2/(1+||v||^2)
    float a = p * scale;

    out[b * OUT + t] = a;
    g_S[b * OUT + t] += a;
    g_preact[b * OUT + t] = 0.0f;                    // ready for next pass
}

// ---------------------------------------------------------------- launch
extern "C" void kernel_launch(void* const* d_in, const int* in_sizes, int n_in,
                              void* d_out, int out_size) {
    const float* x    = (const float*)d_in[0];   // [64, 2048, 8]
    const float* W    = (const float*)d_in[1];   // [2048, 8, 512]
    const float* bias = (const float*)d_in[2];   // [32, 16]
    float* out = (float*)d_out;                  // [64, 32, 16]

    k_zero<<<64, 512>>>();
    k_votes<<<NI, 256>>>(x, W);
    for (int r = 0; r < 3; r++) {
        k_route<<<dim3(ICH, NB), WPB * 32>>>();
        k_squash<<<NB, 512>>>(bias, out);
    }
}

// round 2
// speedup vs baseline: 1.6206x; 1.6206x over previous
#include <cuda_runtime.h>
#include <math.h>

#define NB    64
#define NI    2048
#define KA    8
#define NO    32
#define OA    16
#define OUT   512            // NO*OA

#define I_TILE 32
#define B_TILE 32
#define BPW    4             // b per warp (8 warps * 4 = 32)
#define SMEM_W_BYTES   (2 * KA * OUT * 4)        // 32 KB double-buffered W tile
#define SMEM_S_BYTES   (B_TILE * OUT * 4)        // 64 KB S tile
#define SMEM_BYTES     (SMEM_W_BYTES + SMEM_S_BYTES)

__device__ float g_S[NB * OUT];       // cumulative sum of activations
__device__ float g_preact[NB * OUT];

typedef unsigned long long u64;

// ---- f32x2 helpers (Blackwell packed fp32) ----
__device__ __forceinline__ u64 fma2(u64 a, u64 b, u64 c) {
    u64 d; asm("fma.rn.f32x2 %0, %1, %2, %3;" : "=l"(d) : "l"(a), "l"(b), "l"(c)); return d;
}
__device__ __forceinline__ u64 pack2(float lo, float hi) {
    u64 d; asm("mov.b64 %0, {%1, %2};" : "=l"(d) : "f"(lo), "f"(hi)); return d;
}
__device__ __forceinline__ void unpack2(u64 v, float& lo, float& hi) {
    asm("mov.b64 {%0, %1}, %2;" : "=f"(lo), "=f"(hi) : "l"(v));
}

// ---- cp.async 16B ----
__device__ __forceinline__ void cp16(void* smem_dst, const void* gsrc) {
    unsigned s = (unsigned)__cvta_generic_to_shared(smem_dst);
    asm volatile("cp.async.cg.shared.global [%0], [%1], 16;" :: "r"(s), "l"(gsrc));
}

// 128B-row XOR swizzle: toggles byte bits [4:7) with bits [7:10). Keeps 16B alignment.
__device__ __forceinline__ int swz(int b) { return b ^ ((b >> 3) & 0x70); }

// ---------------------------------------------------------------- zero
__global__ void k_zero() {
    int t = blockIdx.x * blockDim.x + threadIdx.x;
    if (t < NB * OUT) { g_S[t] = 0.0f; g_preact[t] = 0.0f; }
}

// ---------------------------------------------------------------- fused route
// grid = (NI/I_TILE=64, NB/B_TILE=2) = 128 blocks, block = 256 (8 warps).
// lane = j (output capsule). Warp w owns b = bt0 + w*4 + {0..3}.
// Per i: W[i] staged in smem (cp.async double buffer), votes recomputed in regs,
// logits = votes . S, leaky softmax over 32 lanes, preact accumulated in regs,
// flushed once per block with atomics.
template<bool PASS0>
__global__ void __launch_bounds__(256, 1)
k_route(const float* __restrict__ x, const float* __restrict__ W) {
    extern __shared__ char sm[];
    char* Wbase = sm;                    // [2][16KB]
    char* Sbase = sm + SMEM_W_BYTES;     // [32][512] floats (swizzled)

    const int it0  = blockIdx.x * I_TILE;
    const int bt0  = blockIdx.y * B_TILE;
    const int tid  = threadIdx.x;
    const int w    = tid >> 5;
    const int lane = tid & 31;

    // Stage S tile (swizzled) — not needed for pass 0 (route is uniform 1/33).
    if (!PASS0) {
        const float4* src = (const float4*)&g_S[bt0 * OUT];
#pragma unroll
        for (int r = 0; r < 16; r++) {
            int f4 = tid + 256 * r;                 // 4096 float4
            *(float4*)(Sbase + swz(f4 * 16)) = src[f4];
        }
    }

    // Prefetch W[it0] into buffer 0.
    {
        const float4* g = (const float4*)(W + (size_t)it0 * KA * OUT);
#pragma unroll
        for (int r = 0; r < 4; r++) {
            int f4 = tid + 256 * r;                 // 1024 float4 = 16 KB
            cp16(Wbase + swz(f4 * 16), &g[f4]);
        }
        asm volatile("cp.async.commit_group;" ::: "memory");
    }

    u64 acc[BPW][8];
#pragma unroll
    for (int bq = 0; bq < BPW; bq++)
#pragma unroll
        for (int p = 0; p < 8; p++) acc[bq][p] = 0ull;

    for (int ii = 0; ii < I_TILE; ii++) {
        asm volatile("cp.async.wait_group 0;" ::: "memory");
        __syncthreads();   // current buffer ready; all warps done with previous buffer

        // Prefetch next W tile into the other buffer.
        if (ii + 1 < I_TILE) {
            const float4* g = (const float4*)(W + (size_t)(it0 + ii + 1) * KA * OUT);
            char* dst = Wbase + ((ii + 1) & 1) * (KA * OUT * 4);
#pragma unroll
            for (int r = 0; r < 4; r++) {
                int f4 = tid + 256 * r;
                cp16(dst + swz(f4 * 16), &g[f4]);
            }
            asm volatile("cp.async.commit_group;" ::: "memory");
        }

        const char* Wc = Wbase + (ii & 1) * (KA * OUT * 4);
        const int i = it0 + ii;

        // x[b, i, 0..8) for this warp's 4 b (uniform across lanes -> broadcast)
        float xk[BPW][KA];
#pragma unroll
        for (int bq = 0; bq < BPW; bq++) {
            const int b = bt0 + w * BPW + bq;
            const float4* xp = (const float4*)&x[((size_t)b * NI + i) * KA];
            float4 x0 = __ldg(xp), x1 = __ldg(xp + 1);
            xk[bq][0] = x0.x; xk[bq][1] = x0.y; xk[bq][2] = x0.z; xk[bq][3] = x0.w;
            xk[bq][4] = x1.x; xk[bq][5] = x1.y; xk[bq][6] = x1.z; xk[bq][7] = x1.w;
        }

        // votes: v[bq][p] (p = atom pair, 8 pairs = 16 atoms of capsule j=lane)
        u64 v[BPW][8];
#pragma unroll
        for (int bq = 0; bq < BPW; bq++)
#pragma unroll
            for (int p = 0; p < 8; p++) v[bq][p] = 0ull;

#pragma unroll
        for (int k = 0; k < KA; k++) {
            u64 xb[BPW];
#pragma unroll
            for (int bq = 0; bq < BPW; bq++) xb[bq] = pack2(xk[bq][k], xk[bq][k]);
#pragma unroll
            for (int q = 0; q < 4; q++) {
                float4 w4 = *(const float4*)(Wc + swz(k * 2048 + lane * 64 + q * 16));
                u64 w01 = pack2(w4.x, w4.y);
                u64 w23 = pack2(w4.z, w4.w);
#pragma unroll
                for (int bq = 0; bq < BPW; bq++) {
                    v[bq][2 * q]     = fma2(xb[bq], w01, v[bq][2 * q]);
                    v[bq][2 * q + 1] = fma2(xb[bq], w23, v[bq][2 * q + 1]);
                }
            }
        }

        // routing: logit -> leaky softmax -> accumulate
#pragma unroll
        for (int bq = 0; bq < BPW; bq++) {
            float r;
            if (PASS0) {
                r = 1.0f / 33.0f;   // softmax of all-zero logits incl. leak
            } else {
                const int bl = w * BPW + bq;
                u64 lg2 = 0ull;
#pragma unroll
                for (int q = 0; q < 4; q++) {
                    float4 s4 = *(const float4*)(Sbase + swz(bl * 2048 + lane * 64 + q * 16));
                    lg2 = fma2(v[bq][2 * q],     pack2(s4.x, s4.y), lg2);
                    lg2 = fma2(v[bq][2 * q + 1], pack2(s4.z, s4.w), lg2);
                }
                float a0, a1; unpack2(lg2, a0, a1);
                float lg = a0 + a1;
                float e = __expf(lg);
                float tot = e;
#pragma unroll
                for (int d = 16; d > 0; d >>= 1)
                    tot += __shfl_xor_sync(0xFFFFFFFFu, tot, d);
                r = __fdividef(e, 1.0f + tot);   // leaky softmax (leak logit = 0)
            }
            u64 r2 = pack2(r, r);
#pragma unroll
            for (int p = 0; p < 8; p++)
                acc[bq][p] = fma2(r2, v[bq][p], acc[bq][p]);
        }
    }

    // Flush accumulated preact contributions.
#pragma unroll
    for (int bq = 0; bq < BPW; bq++) {
        const int b = bt0 + w * BPW + bq;
        float* dst = &g_preact[(size_t)b * OUT + lane * OA];
#pragma unroll
        for (int p = 0; p < 8; p++) {
            float a0, a1; unpack2(acc[bq][p], a0, a1);
            atomicAdd(dst + 2 * p,     a0);
            atomicAdd(dst + 2 * p + 1, a1);
        }
    }
}

// ---------------------------------------------------------------- squash
// grid = 64 (b), block = 512. thread t -> (j = t/16, a = t%16).
__global__ void k_squash(const float* __restrict__ bias, float* __restrict__ out) {
    const int b = blockIdx.x;
    const int t = threadIdx.x;

    float p = g_preact[b * OUT + t] + bias[t];
    float sq = p * p;
#pragma unroll
    for (int d = 1; d < OA; d <<= 1)
        sq += __shfl_xor_sync(0xFFFFFFFFu, sq, d);   // sum over 16-lane group
    float nrm = sqrtf(sq);
    float scale = nrm / (1.0f + sq);                 // v/||v|| * ||v||^2/(1+||v||^2)
    float a = p * scale;

    out[b * OUT + t] = a;
    g_S[b * OUT + t] += a;
    g_preact[b * OUT + t] = 0.0f;                    // ready for next pass
}

// ---------------------------------------------------------------- launch
extern "C" void kernel_launch(void* const* d_in, const int* in_sizes, int n_in,
                              void* d_out, int out_size) {
    const float* x    = (const float*)d_in[0];   // [64, 2048, 8]
    const float* W    = (const float*)d_in[1];   // [2048, 8, 512]
    const float* bias = (const float*)d_in[2];   // [32, 16]
    float* out = (float*)d_out;                  // [64, 32, 16]

    cudaFuncSetAttribute(k_route<true>,  cudaFuncAttributeMaxDynamicSharedMemorySize, SMEM_BYTES);
    cudaFuncSetAttribute(k_route<false>, cudaFuncAttributeMaxDynamicSharedMemorySize, SMEM_BYTES);

    dim3 grid(NI / I_TILE, NB / B_TILE);

    k_zero<<<64, 512>>>();
    k_route<true><<<grid, 256, SMEM_BYTES>>>(x, W);
    k_squash<<<NB, 512>>>(bias, out);
    k_route<false><<<grid, 256, SMEM_BYTES>>>(x, W);
    k_squash<<<NB, 512>>>(bias, out);
    k_route<false><<<grid, 256, SMEM_BYTES>>>(x, W);
    k_squash<<<NB, 512>>>(bias, out);
}